// round 5
// baseline (speedup 1.0000x reference)
#include <cuda_runtime.h>

typedef unsigned long long ull;

__device__ __forceinline__ ull pack2(float lo, float hi) {
    ull r; asm("mov.b64 %0, {%1, %2};" : "=l"(r) : "f"(lo), "f"(hi)); return r;
}
__device__ __forceinline__ void unpack2(ull v, float& lo, float& hi) {
    asm("mov.b64 {%0, %1}, %2;" : "=f"(lo), "=f"(hi) : "l"(v));
}
// Packed fp32x2 FMA (Blackwell): 2 FMAs per issue slot, 2x scalar FFMA throughput.
__device__ __forceinline__ ull fma2(ull a, ull b, ull c) {
    ull d; asm("fma.rn.f32x2 %0, %1, %2, %3;" : "=l"(d) : "l"(a), "l"(b), "l"(c)); return d;
}
__device__ __forceinline__ float leaky(float x) { return fmaxf(x, 0.01f * x); }
__device__ __forceinline__ float softplus_f(float x) {
    // jax.nn.softplus(x) = logaddexp(x, 0) = max(x,0) + log1p(exp(-|x|))
    return fmaxf(x, 0.0f) + log1pf(expf(-fabsf(x)));
}

// Per row: h1 = leaky(W1 q + b1); h2 = leaky(W2 h1 + b2);
// Ld = softplus(W_Ld h2 + b_Ld) (2); Lo = W_Lo h2 + b_Lo (1);
// L = [[Ld0,0],[Lo,Ld1]]; H = L L^T + 1e-9 I  ->  4 floats out per row.
__global__ __launch_bounds__(256, 2)
void dln_kernel(const float4* __restrict__ x,
                const float* __restrict__ W1, const float* __restrict__ b1,
                const float* __restrict__ W2, const float* __restrict__ b2,
                const float* __restrict__ WLd, const float* __restrict__ bLd,
                const float* __restrict__ WLo, const float* __restrict__ bLo,
                float4* __restrict__ out, int n)
{
    __shared__ __align__(16) float sW2[64 * 64];   // row-major: pairs along k contiguous
    __shared__ ull  sW1t[4 * 32];   // [k][j2] = (W1[2j2][k], W1[2j2+1][k])
    __shared__ ull  sb1p[32];       // (b1[2j2], b1[2j2+1])
    __shared__ ull  sLdp[64];       // (WLd[0][j], WLd[1][j])
    __shared__ float sWLo[64];
    __shared__ float sb2[64];
    __shared__ float sbh[4];

    const int tid = threadIdx.x;

    for (int i = tid; i < 64 * 64; i += 256) sW2[i] = W2[i];
    for (int i = tid; i < 128; i += 256) {
        int k = i >> 5, j2 = i & 31;
        sW1t[i] = pack2(W1[(2 * j2) * 4 + k], W1[(2 * j2 + 1) * 4 + k]);
    }
    for (int i = tid; i < 64; i += 256) {
        sb2[i]  = b2[i];
        sLdp[i] = pack2(WLd[i], WLd[64 + i]);
        sWLo[i] = WLo[i];
        if (i < 32) sb1p[i] = pack2(b1[2 * i], b1[2 * i + 1]);
    }
    if (tid == 0) { sbh[0] = bLd[0]; sbh[1] = bLd[1]; sbh[2] = bLo[0]; sbh[3] = 0.f; }
    __syncthreads();

    for (int row = blockIdx.x * 256 + tid; row < n; row += gridDim.x * 256) {
        float4 q = x[row];
        ull q0 = pack2(q.x, q.x), q1 = pack2(q.y, q.y),
            q2 = pack2(q.z, q.z), q3 = pack2(q.w, q.w);

        // ---- layer 1: 128 FFMA2, outputs packed pairwise over neurons ----
        ull h1p[32];
        #pragma unroll
        for (int j2 = 0; j2 < 32; ++j2) {
            ull acc = sb1p[j2];
            acc = fma2(sW1t[j2],       q0, acc);
            acc = fma2(sW1t[32 + j2],  q1, acc);
            acc = fma2(sW1t[64 + j2],  q2, acc);
            acc = fma2(sW1t[96 + j2],  q3, acc);
            float lo, hi; unpack2(acc, lo, hi);
            h1p[j2] = pack2(leaky(lo), leaky(hi));
        }

        // ---- layer 2 + heads fused: 64 x (32 FFMA2 + epilogue) ----
        ull  accLd = 0ull;   // packed (d_Ld0, d_Ld1)
        float accLo = 0.f;
        #pragma unroll 2
        for (int j = 0; j < 64; ++j) {
            const ulonglong2* w = reinterpret_cast<const ulonglong2*>(sW2 + (j << 6));
            ull a0 = 0ull, a1 = 0ull;   // two chains hide FFMA latency
            #pragma unroll
            for (int k4 = 0; k4 < 16; ++k4) {
                ulonglong2 v = w[k4];                 // LDS.128, uniform addr -> broadcast
                a0 = fma2(v.x, h1p[2 * k4],     a0);
                a1 = fma2(v.y, h1p[2 * k4 + 1], a1);
            }
            float l0, m0, l1, m1;
            unpack2(a0, l0, m0); unpack2(a1, l1, m1);
            float h = leaky((l0 + m0) + (l1 + m1) + sb2[j]);
            accLd = fma2(sLdp[j], pack2(h, h), accLd);
            accLo = fmaf(sWLo[j], h, accLo);
        }

        float d0, d1; unpack2(accLd, d0, d1);
        float Ld0 = softplus_f(d0 + sbh[0]);
        float Ld1 = softplus_f(d1 + sbh[1]);
        float Lo  = accLo + sbh[2];

        float H00 = fmaf(Ld0, Ld0, 1e-9f);
        float H01 = Ld0 * Lo;
        float H11 = fmaf(Lo, Lo, fmaf(Ld1, Ld1, 1e-9f));
        out[row] = make_float4(H00, H01, H01, H11);
    }
}

extern "C" void kernel_launch(void* const* d_in, const int* in_sizes, int n_in,
                              void* d_out, int out_size) {
    const float4* x  = (const float4*)d_in[0];
    const float* W1  = (const float*)d_in[1];
    const float* b1  = (const float*)d_in[2];
    const float* W2  = (const float*)d_in[3];
    const float* b2  = (const float*)d_in[4];
    const float* WLd = (const float*)d_in[5];
    const float* bLd = (const float*)d_in[6];
    const float* WLo = (const float*)d_in[7];
    const float* bLo = (const float*)d_in[8];

    int n = in_sizes[0] / 4;
    // Persistent single wave: 148 SMs x 2 CTAs/SM, grid-stride over rows.
    int blocks = 296;
    dln_kernel<<<blocks, 256>>>(x, W1, b1, W2, b2, WLd, bLd, WLo, bLo,
                                (float4*)d_out, n);
}

// round 7
// speedup vs baseline: 1.0415x; 1.0415x over previous
#include <cuda_runtime.h>

typedef unsigned long long ull;

__device__ __forceinline__ ull pack2(float lo, float hi) {
    ull r; asm("mov.b64 %0, {%1, %2};" : "=l"(r) : "f"(lo), "f"(hi)); return r;
}
__device__ __forceinline__ void unpack2(ull v, float& lo, float& hi) {
    asm("mov.b64 {%0, %1}, %2;" : "=f"(lo), "=f"(hi) : "l"(v));
}
// Packed fp32x2 FMA (Blackwell): 2 FMAs per issue slot.
__device__ __forceinline__ ull fma2(ull a, ull b, ull c) {
    ull d; asm("fma.rn.f32x2 %0, %1, %2, %3;" : "=l"(d) : "l"(a), "l"(b), "l"(c)); return d;
}
__device__ __forceinline__ float leaky(float x) { return fmaxf(x, 0.01f * x); }
__device__ __forceinline__ float softplus_f(float x) {
    return fmaxf(x, 0.0f) + log1pf(expf(-fabsf(x)));
}

// R=2 rows per thread: every shared weight load is amortized over 2 rows.
__global__ __launch_bounds__(128, 2)
void dln_kernel(const float4* __restrict__ x,
                const float* __restrict__ W1, const float* __restrict__ b1,
                const float* __restrict__ W2, const float* __restrict__ b2,
                const float* __restrict__ WLd, const float* __restrict__ bLd,
                const float* __restrict__ WLo, const float* __restrict__ bLo,
                float4* __restrict__ out, int n)
{
    __shared__ __align__(16) float sW2[64 * 64];   // row-major, 16B-vectorizable
    __shared__ __align__(16) ulonglong2 sW1[64];   // [2*j2+h]: h=0 -> {wk0, wk1}, h=1 -> {wk2, wk3}
    __shared__ ull sb1p[32];                       // (b1[2j2], b1[2j2+1])
    __shared__ __align__(16) ulonglong2 sEp[64];   // { (WLd0[j],WLd1[j]), (b2[j],WLo[j]) }
    __shared__ float sbh[4];

    const int tid = threadIdx.x;

    for (int i = tid; i < 64 * 64; i += 128) sW2[i] = W2[i];
    for (int j2 = tid; j2 < 32; j2 += 128) {
        ull w0 = pack2(W1[(2 * j2) * 4 + 0], W1[(2 * j2 + 1) * 4 + 0]);
        ull w1 = pack2(W1[(2 * j2) * 4 + 1], W1[(2 * j2 + 1) * 4 + 1]);
        ull w2 = pack2(W1[(2 * j2) * 4 + 2], W1[(2 * j2 + 1) * 4 + 2]);
        ull w3 = pack2(W1[(2 * j2) * 4 + 3], W1[(2 * j2 + 1) * 4 + 3]);
        sW1[2 * j2]     = make_ulonglong2(w0, w1);
        sW1[2 * j2 + 1] = make_ulonglong2(w2, w3);
        sb1p[j2] = pack2(b1[2 * j2], b1[2 * j2 + 1]);
    }
    for (int j = tid; j < 64; j += 128)
        sEp[j] = make_ulonglong2(pack2(WLd[j], WLd[64 + j]), pack2(b2[j], WLo[j]));
    if (tid == 0) { sbh[0] = bLd[0]; sbh[1] = bLd[1]; sbh[2] = bLo[0]; sbh[3] = 0.f; }
    __syncthreads();

    const int rowsPerIter = gridDim.x * 256;       // 128 threads x 2 rows per block
    for (int base = blockIdx.x * 256; base < n; base += rowsPerIter) {
        const int rA = base + tid;
        const int rB = rA + 128;
        if (rA >= n) break;
        const bool hasB = (rB < n);

        float4 qa = x[rA];
        float4 qb = hasB ? x[rB] : qa;

        ull qa0 = pack2(qa.x, qa.x), qa1 = pack2(qa.y, qa.y),
            qa2 = pack2(qa.z, qa.z), qa3 = pack2(qa.w, qa.w);
        ull qb0 = pack2(qb.x, qb.x), qb1 = pack2(qb.y, qb.y),
            qb2 = pack2(qb.z, qb.z), qb3 = pack2(qb.w, qb.w);

        // ---- layer 1 for both rows (weights loaded once) ----
        ull h1a[32], h1b[32];
        #pragma unroll
        for (int j2 = 0; j2 < 32; ++j2) {
            ulonglong2 wA = sW1[2 * j2];
            ulonglong2 wB = sW1[2 * j2 + 1];
            ull bb = sb1p[j2];
            ull A = fma2(wA.x, qa0, bb);
            ull B = fma2(wA.x, qb0, bb);
            A = fma2(wA.y, qa1, A);   B = fma2(wA.y, qb1, B);
            A = fma2(wB.x, qa2, A);   B = fma2(wB.x, qb2, B);
            A = fma2(wB.y, qa3, A);   B = fma2(wB.y, qb3, B);
            float lo, hi;
            unpack2(A, lo, hi); h1a[j2] = pack2(leaky(lo), leaky(hi));
            unpack2(B, lo, hi); h1b[j2] = pack2(leaky(lo), leaky(hi));
        }

        // ---- layer 2 + heads, fused; 4 FFMA2 per LDS.128 ----
        ull  aLd = 0ull, bLd2 = 0ull;
        float aLo = 0.f, bLo2 = 0.f;
        #pragma unroll 2
        for (int j = 0; j < 64; ++j) {
            const ulonglong2* w = reinterpret_cast<const ulonglong2*>(sW2 + (j << 6));
            ull a0 = 0ull, a1 = 0ull, b0 = 0ull, b1c = 0ull;
            #pragma unroll
            for (int k4 = 0; k4 < 16; ++k4) {
                ulonglong2 v = w[k4];              // broadcast LDS.128
                a0  = fma2(v.x, h1a[2 * k4],     a0);
                a1  = fma2(v.y, h1a[2 * k4 + 1], a1);
                b0  = fma2(v.x, h1b[2 * k4],     b0);
                b1c = fma2(v.y, h1b[2 * k4 + 1], b1c);
            }
            ulonglong2 ep = sEp[j];
            float e_b2, e_wlo; unpack2(ep.y, e_b2, e_wlo);
            float l0, m0, l1, m1;
            unpack2(a0, l0, m0); unpack2(a1, l1, m1);
            float hA = leaky((l0 + m0) + (l1 + m1) + e_b2);
            unpack2(b0, l0, m0); unpack2(b1c, l1, m1);
            float hB = leaky((l0 + m0) + (l1 + m1) + e_b2);
            aLd  = fma2(ep.x, pack2(hA, hA), aLd);
            bLd2 = fma2(ep.x, pack2(hB, hB), bLd2);
            aLo  = fmaf(e_wlo, hA, aLo);
            bLo2 = fmaf(e_wlo, hB, bLo2);
        }

        // ---- Cholesky product epilogue, row A ----
        {
            float d0, d1; unpack2(aLd, d0, d1);
            float Ld0 = softplus_f(d0 + sbh[0]);
            float Ld1 = softplus_f(d1 + sbh[1]);
            float Lo  = aLo + sbh[2];
            float H00 = fmaf(Ld0, Ld0, 1e-9f);
            float H01 = Ld0 * Lo;
            float H11 = fmaf(Lo, Lo, fmaf(Ld1, Ld1, 1e-9f));
            out[rA] = make_float4(H00, H01, H01, H11);
        }
        // ---- row B ----
        if (hasB) {
            float d0, d1; unpack2(bLd2, d0, d1);
            float Ld0 = softplus_f(d0 + sbh[0]);
            float Ld1 = softplus_f(d1 + sbh[1]);
            float Lo  = bLo2 + sbh[2];
            float H00 = fmaf(Ld0, Ld0, 1e-9f);
            float H01 = Ld0 * Lo;
            float H11 = fmaf(Lo, Lo, fmaf(Ld1, Ld1, 1e-9f));
            out[rB] = make_float4(H00, H01, H01, H11);
        }
    }
}

extern "C" void kernel_launch(void* const* d_in, const int* in_sizes, int n_in,
                              void* d_out, int out_size) {
    const float4* x  = (const float4*)d_in[0];
    const float* W1  = (const float*)d_in[1];
    const float* b1  = (const float*)d_in[2];
    const float* W2  = (const float*)d_in[3];
    const float* b2  = (const float*)d_in[4];
    const float* WLd = (const float*)d_in[5];
    const float* bLd = (const float*)d_in[6];
    const float* WLo = (const float*)d_in[7];
    const float* bLo = (const float*)d_in[8];

    int n = in_sizes[0] / 4;
    // 1024 blocks: with n=1M each block does exactly 4 grid-stride iterations
    // (4096 block-iters of 256 rows), even work per block.
    int blocks = 1024;
    dln_kernel<<<blocks, 128>>>(x, W1, b1, W2, b2, WLd, bLd, WLo, bLo,
                                (float4*)d_out, n);
}

// round 9
// speedup vs baseline: 3.9848x; 3.8259x over previous
#include <cuda_runtime.h>
#include <cuda_bf16.h>
#include <cstdint>

typedef unsigned long long ull;

__device__ __forceinline__ ull pack2(float lo, float hi) {
    ull r; asm("mov.b64 %0, {%1, %2};" : "=l"(r) : "f"(lo), "f"(hi)); return r;
}
__device__ __forceinline__ void unpack2(ull v, float& lo, float& hi) {
    asm("mov.b64 {%0, %1}, %2;" : "=f"(lo), "=f"(hi) : "l"(v));
}
__device__ __forceinline__ ull fma2(ull a, ull b, ull c) {
    ull d; asm("fma.rn.f32x2 %0, %1, %2, %3;" : "=l"(d) : "l"(a), "l"(b), "l"(c)); return d;
}
__device__ __forceinline__ float leaky(float x) { return fmaxf(x, 0.01f * x); }
__device__ __forceinline__ float softplus_f(float x) {
    return fmaxf(x, 0.0f) + log1pf(expf(-fabsf(x)));
}
__device__ __forceinline__ uint32_t smem_u32(const void* p) {
    uint32_t a;
    asm("{ .reg .u64 t; cvta.to.shared.u64 t, %1; cvt.u32.u64 %0, t; }" : "=r"(a) : "l"(p));
    return a;
}

#define SW128(off) ((off) ^ (((off) >> 3) & 0x70))

// mma.sync m16n8k16 row.col f32 += bf16*bf16 (baseline PTX, works on compute_103)
#define MMA16816(d, a, b0v, b1v) \
    asm volatile("mma.sync.aligned.m16n8k16.row.col.f32.bf16.bf16.f32 " \
        "{%0,%1,%2,%3}, {%4,%5,%6,%7}, {%8,%9}, {%0,%1,%2,%3};" \
        : "+f"((d)[0]), "+f"((d)[1]), "+f"((d)[2]), "+f"((d)[3]) \
        : "r"((a)[0]), "r"((a)[1]), "r"((a)[2]), "r"((a)[3]), "r"(b0v), "r"(b1v))

static constexpr int DYN_SMEM = 1024 + 2 * 8192;   // align pad + W2hi + W2lo (SW128)

__global__ __launch_bounds__(128, 2)
void dln_mma(const float4* __restrict__ x,
             const float* __restrict__ W1, const float* __restrict__ b1,
             const float* __restrict__ W2, const float* __restrict__ b2,
             const float* __restrict__ WLd, const float* __restrict__ bLd,
             const float* __restrict__ WLo, const float* __restrict__ bLo,
             float4* __restrict__ out, int n)
{
    extern __shared__ char dyn[];
    __shared__ __align__(16) ulonglong2 sW1a[32], sW1b[32];  // (W1[2jp][k],W1[2jp+1][k]) pairs
    __shared__ ull sb1p[32];
    __shared__ __align__(16) ulonglong2 sEp[64];             // {(WLd0,WLd1),(b2,WLo)} per j
    __shared__ float sbh[4];

    const int tid  = threadIdx.x;
    const int wid  = tid >> 5;
    const int lane = tid & 31;
    const int c    = lane & 3;    // quad col id (t%4)
    const int rq   = lane >> 2;   // group id (t/4)

    const uint32_t dbase = smem_u32(dyn);
    const uint32_t whi = (dbase + 1023u) & ~1023u;
    const uint32_t wlo = whi + 8192u;

    // ---- prep: W2 -> bf16 hi/lo SW128 tiles (rows j, 128B each); small weights ----
    for (int i = tid; i < 4096; i += 128) {
        float w = W2[i];
        uint16_t hb; asm("cvt.rn.bf16.f32 %0, %1;" : "=h"(hb) : "f"(w));
        float hf = __uint_as_float(((uint32_t)hb) << 16);
        float lf = w - hf;                 // exact residual (Sterbenz)
        uint16_t lb; asm("cvt.rn.bf16.f32 %0, %1;" : "=h"(lb) : "f"(lf));
        uint32_t off = SW128((uint32_t)(((i >> 6) * 128) + ((i & 63) * 2)));
        asm volatile("st.shared.u16 [%0], %1;" :: "r"(whi + off), "h"(hb));
        asm volatile("st.shared.u16 [%0], %1;" :: "r"(wlo + off), "h"(lb));
    }
    for (int jp = tid; jp < 32; jp += 128) {
        sW1a[jp] = make_ulonglong2(pack2(W1[(2*jp)*4+0], W1[(2*jp+1)*4+0]),
                                   pack2(W1[(2*jp)*4+1], W1[(2*jp+1)*4+1]));
        sW1b[jp] = make_ulonglong2(pack2(W1[(2*jp)*4+2], W1[(2*jp+1)*4+2]),
                                   pack2(W1[(2*jp)*4+3], W1[(2*jp+1)*4+3]));
        sb1p[jp] = pack2(b1[2*jp], b1[2*jp+1]);
    }
    for (int j = tid; j < 64; j += 128)
        sEp[j] = make_ulonglong2(pack2(WLd[j], WLd[64+j]), pack2(b2[j], WLo[j]));
    if (tid == 0) { sbh[0] = bLd[0]; sbh[1] = bLd[1]; sbh[2] = bLo[0]; sbh[3] = 0.f; }
    __syncthreads();

    const int ntiles = (n + 127) >> 7;
    for (int t = blockIdx.x; t < ntiles; t += gridDim.x) {
        const int gbase = (t << 7) + (wid << 5);   // warp's 32-row tile start

        // ---- load q for the 4 row-slots this thread touches; pre-broadcast pack ----
        ull qp[16];
        #pragma unroll
        for (int s = 0; s < 4; ++s) {
            int gr = gbase + rq + 8 * s;
            if (gr > n - 1) gr = n - 1;
            float4 q = x[gr];
            qp[4*s+0] = pack2(q.x, q.x);
            qp[4*s+1] = pack2(q.y, q.y);
            qp[4*s+2] = pack2(q.z, q.z);
            qp[4*s+3] = pack2(q.w, q.w);
        }

        float D[2][8][4];
        #pragma unroll
        for (int m = 0; m < 2; ++m)
            #pragma unroll
            for (int nt = 0; nt < 8; ++nt)
                #pragma unroll
                for (int i = 0; i < 4; ++i) D[m][nt][i] = 0.f;

        #pragma unroll
        for (int kt = 0; kt < 4; ++kt) {
            // ---- A fragments computed IN PLACE (no staging): layer-1 fp32 + hi/lo split ----
            uint32_t ahi[2][4], alo[2][4];
            #pragma unroll
            for (int h = 0; h < 2; ++h) {
                int jp = c + 8 * kt + 4 * h;        // col-pair index (cols 2jp, 2jp+1)
                ulonglong2 wA = sW1a[jp], wB = sW1b[jp];
                ull bb = sb1p[jp];
                #pragma unroll
                for (int s = 0; s < 4; ++s) {       // row slots rq+8s
                    ull z = fma2(wA.x, qp[4*s+0], bb);
                    z = fma2(wA.y, qp[4*s+1], z);
                    z = fma2(wB.x, qp[4*s+2], z);
                    z = fma2(wB.y, qp[4*s+3], z);
                    float e, o; unpack2(z, e, o);
                    e = leaky(e); o = leaky(o);
                    uint32_t hv;                     // lo half = even col, hi half = odd col
                    asm("cvt.rn.bf16x2.f32 %0, %1, %2;" : "=r"(hv) : "f"(o), "f"(e));
                    float ef = __uint_as_float(hv << 16);
                    float of = __uint_as_float(hv & 0xFFFF0000u);
                    float le = e - ef, lod = o - of;
                    uint32_t lv;
                    asm("cvt.rn.bf16x2.f32 %0, %1, %2;" : "=r"(lv) : "f"(lod), "f"(le));
                    int m = s >> 1, half = s & 1;    // frag idx: 2h+half
                    ahi[m][2*h + half] = hv;
                    alo[m][2*h + half] = lv;
                }
            }

            // ---- B frags via ldmatrix (2 n-tiles per x4), 3-product compensated MMA ----
            #pragma unroll
            for (int p = 0; p < 4; ++p) {
                int mat = lane >> 3, rin = lane & 7;
                int nrow = (2*p + (mat >> 1)) * 8 + rin;
                int kseg = 2*kt + (mat & 1);
                uint32_t off = SW128((uint32_t)(nrow * 128 + kseg * 16));
                uint32_t bh0, bh1, bh2, bh3, bl0, bl1, bl2, bl3;
                asm volatile("ldmatrix.sync.aligned.m8n8.x4.shared.b16 {%0,%1,%2,%3}, [%4];"
                    : "=r"(bh0), "=r"(bh1), "=r"(bh2), "=r"(bh3) : "r"(whi + off));
                asm volatile("ldmatrix.sync.aligned.m8n8.x4.shared.b16 {%0,%1,%2,%3}, [%4];"
                    : "=r"(bl0), "=r"(bl1), "=r"(bl2), "=r"(bl3) : "r"(wlo + off));
                #pragma unroll
                for (int m = 0; m < 2; ++m) {
                    MMA16816(D[m][2*p],     ahi[m], bh0, bh1);   // hi*hi
                    MMA16816(D[m][2*p],     ahi[m], bl0, bl1);   // hi*lo
                    MMA16816(D[m][2*p],     alo[m], bh0, bh1);   // lo*hi
                    MMA16816(D[m][2*p + 1], ahi[m], bh2, bh3);
                    MMA16816(D[m][2*p + 1], ahi[m], bl2, bl3);
                    MMA16816(D[m][2*p + 1], alo[m], bh2, bh3);
                }
            }
        }

        // ---- epilogue: +b2, leaky, head dots (fp32), per row-slot accumulators ----
        ull  accLd[4] = {0ull, 0ull, 0ull, 0ull};   // packed (Ld0, Ld1) sums
        float accLo[4] = {0.f, 0.f, 0.f, 0.f};
        #pragma unroll
        for (int m = 0; m < 2; ++m) {
            #pragma unroll
            for (int nt = 0; nt < 8; ++nt) {
                int j0 = 8 * nt + 2 * c;
                ulonglong2 ep0 = sEp[j0], ep1 = sEp[j0 + 1];
                float b20, wl0; unpack2(ep0.y, b20, wl0);
                float b21, wl1; unpack2(ep1.y, b21, wl1);
                float h00 = leaky(D[m][nt][0] + b20);
                float h01 = leaky(D[m][nt][1] + b21);
                float h10 = leaky(D[m][nt][2] + b20);
                float h11 = leaky(D[m][nt][3] + b21);
                accLd[2*m]   = fma2(ep0.x, pack2(h00, h00), accLd[2*m]);
                accLd[2*m]   = fma2(ep1.x, pack2(h01, h01), accLd[2*m]);
                accLd[2*m+1] = fma2(ep0.x, pack2(h10, h10), accLd[2*m+1]);
                accLd[2*m+1] = fma2(ep1.x, pack2(h11, h11), accLd[2*m+1]);
                accLo[2*m]   = fmaf(wl0, h00, fmaf(wl1, h01, accLo[2*m]));
                accLo[2*m+1] = fmaf(wl0, h10, fmaf(wl1, h11, accLo[2*m+1]));
            }
        }

        // ---- quad all-reduce (bfly), lane c finalizes row rq + 8c ----
        float v0 = 0.f, v1 = 0.f, v2 = 0.f;
        #pragma unroll
        for (int s = 0; s < 4; ++s) {
            float a0, a1; unpack2(accLd[s], a0, a1);
            float a2 = accLo[s];
            #pragma unroll
            for (int msk = 1; msk <= 2; msk <<= 1) {
                a0 += __shfl_xor_sync(0xFFFFFFFFu, a0, msk);
                a1 += __shfl_xor_sync(0xFFFFFFFFu, a1, msk);
                a2 += __shfl_xor_sync(0xFFFFFFFFu, a2, msk);
            }
            if (c == s) { v0 = a0; v1 = a1; v2 = a2; }
        }

        int g = gbase + rq + 8 * c;
        if (g < n) {
            float Ld0 = softplus_f(v0 + sbh[0]);
            float Ld1 = softplus_f(v1 + sbh[1]);
            float Lo  = v2 + sbh[2];
            float H00 = fmaf(Ld0, Ld0, 1e-9f);
            float H01 = Ld0 * Lo;
            float H11 = fmaf(Lo, Lo, fmaf(Ld1, Ld1, 1e-9f));
            out[g] = make_float4(H00, H01, H01, H11);
        }
    }
}

extern "C" void kernel_launch(void* const* d_in, const int* in_sizes, int n_in,
                              void* d_out, int out_size) {
    const float4* x  = (const float4*)d_in[0];
    const float* W1  = (const float*)d_in[1];
    const float* b1  = (const float*)d_in[2];
    const float* W2  = (const float*)d_in[3];
    const float* b2  = (const float*)d_in[4];
    const float* WLd = (const float*)d_in[5];
    const float* bLd = (const float*)d_in[6];
    const float* WLo = (const float*)d_in[7];
    const float* bLo = (const float*)d_in[8];

    int n = in_sizes[0] / 4;
    int ntiles = (n + 127) >> 7;
    int blocks = 2048;                 // 4 tiles per CTA at n=1M; amortizes W2 split prep
    if (blocks > ntiles) blocks = ntiles;
    dln_mma<<<blocks, 128, DYN_SMEM>>>(x, W1, b1, W2, b2, WLd, bLd, WLo, bLo,
                                       (float4*)d_out, n);
}

// round 10
// speedup vs baseline: 4.3697x; 1.0966x over previous
#include <cuda_runtime.h>
#include <cuda_bf16.h>
#include <cstdint>

typedef unsigned long long ull;

__device__ __forceinline__ ull pack2(float lo, float hi) {
    ull r; asm("mov.b64 %0, {%1, %2};" : "=l"(r) : "f"(lo), "f"(hi)); return r;
}
__device__ __forceinline__ void unpack2(ull v, float& lo, float& hi) {
    asm("mov.b64 {%0, %1}, %2;" : "=f"(lo), "=f"(hi) : "l"(v));
}
__device__ __forceinline__ ull fma2(ull a, ull b, ull c) {
    ull d; asm("fma.rn.f32x2 %0, %1, %2, %3;" : "=l"(d) : "l"(a), "l"(b), "l"(c)); return d;
}
__device__ __forceinline__ float leaky(float x) { return fmaxf(x, 0.01f * x); }
__device__ __forceinline__ float softplus_f(float x) {
    return fmaxf(x, 0.0f) + log1pf(expf(-fabsf(x)));
}
__device__ __forceinline__ uint32_t smem_u32(const void* p) {
    uint32_t a;
    asm("{ .reg .u64 t; cvta.to.shared.u64 t, %1; cvt.u32.u64 %0, t; }" : "=r"(a) : "l"(p));
    return a;
}

#define SW128(off) ((off) ^ (((off) >> 3) & 0x70))

// mma.sync m16n8k16 row.col f32 += bf16*bf16 (baseline PTX, works on compute_103)
#define MMA16816(d, a, b0v, b1v) \
    asm volatile("mma.sync.aligned.m16n8k16.row.col.f32.bf16.bf16.f32 " \
        "{%0,%1,%2,%3}, {%4,%5,%6,%7}, {%8,%9}, {%0,%1,%2,%3};" \
        : "+f"((d)[0]), "+f"((d)[1]), "+f"((d)[2]), "+f"((d)[3]) \
        : "r"((a)[0]), "r"((a)[1]), "r"((a)[2]), "r"((a)[3]), "r"(b0v), "r"(b1v))

static constexpr int DYN_SMEM = 1024 + 2 * 8192;   // align pad + W2hi + W2lo (SW128)

__global__ __launch_bounds__(128, 3)
void dln_mma(const float4* __restrict__ x,
             const float* __restrict__ W1, const float* __restrict__ b1,
             const float* __restrict__ W2, const float* __restrict__ b2,
             const float* __restrict__ WLd, const float* __restrict__ bLd,
             const float* __restrict__ WLo, const float* __restrict__ bLo,
             float4* __restrict__ out, int n)
{
    extern __shared__ char dyn[];
    __shared__ __align__(16) ulonglong2 sW1a[32], sW1b[32];  // (W1[2jp][k],W1[2jp+1][k]) pairs
    __shared__ ull sb1p[32];
    __shared__ ull sB2p[32];                                 // (b2[2jp], b2[2jp+1])
    __shared__ __align__(16) ulonglong2 sHd[32];             // {(Ld0 pair), (Ld1 pair)}
    __shared__ ull sLoP[32];                                 // (WLo pair)
    __shared__ float sbh[4];

    const int tid  = threadIdx.x;
    const int wid  = tid >> 5;
    const int lane = tid & 31;
    const int c    = lane & 3;    // quad col id
    const int rq   = lane >> 2;   // quad row id

    const uint32_t dbase = smem_u32(dyn);
    const uint32_t whi = (dbase + 1023u) & ~1023u;
    const uint32_t wlo = whi + 8192u;

    // ---- prep: W2 -> bf16 hi/lo SW128 tiles; packed small weights ----
    for (int i = tid; i < 4096; i += 128) {
        float w = W2[i];
        uint16_t hb; asm("cvt.rn.bf16.f32 %0, %1;" : "=h"(hb) : "f"(w));
        float hf = __uint_as_float(((uint32_t)hb) << 16);
        float lf = w - hf;
        uint16_t lb; asm("cvt.rn.bf16.f32 %0, %1;" : "=h"(lb) : "f"(lf));
        uint32_t off = SW128((uint32_t)(((i >> 6) * 128) + ((i & 63) * 2)));
        asm volatile("st.shared.u16 [%0], %1;" :: "r"(whi + off), "h"(hb));
        asm volatile("st.shared.u16 [%0], %1;" :: "r"(wlo + off), "h"(lb));
    }
    for (int jp = tid; jp < 32; jp += 128) {
        sW1a[jp] = make_ulonglong2(pack2(W1[(2*jp)*4+0], W1[(2*jp+1)*4+0]),
                                   pack2(W1[(2*jp)*4+1], W1[(2*jp+1)*4+1]));
        sW1b[jp] = make_ulonglong2(pack2(W1[(2*jp)*4+2], W1[(2*jp+1)*4+2]),
                                   pack2(W1[(2*jp)*4+3], W1[(2*jp+1)*4+3]));
        sb1p[jp] = pack2(b1[2*jp], b1[2*jp+1]);
        sB2p[jp] = pack2(b2[2*jp], b2[2*jp+1]);
        sHd[jp]  = make_ulonglong2(pack2(WLd[2*jp],    WLd[2*jp+1]),
                                   pack2(WLd[64+2*jp], WLd[64+2*jp+1]));
        sLoP[jp] = pack2(WLo[2*jp], WLo[2*jp+1]);
    }
    if (tid == 0) { sbh[0] = bLd[0]; sbh[1] = bLd[1]; sbh[2] = bLo[0]; sbh[3] = 0.f; }
    __syncthreads();

    const ull SLOPE2 = pack2(0.01f, 0.01f);

    const int ntiles = (n + 127) >> 7;
    for (int t = blockIdx.x; t < ntiles; t += gridDim.x) {
        const int gbase = (t << 7) + (wid << 5);

        // ---- per-thread q rows (rq + 8s), pre-broadcast packed ----
        ull qp[16];
        #pragma unroll
        for (int s = 0; s < 4; ++s) {
            int gr = gbase + rq + 8 * s;
            if (gr > n - 1) gr = n - 1;
            float4 q = x[gr];
            qp[4*s+0] = pack2(q.x, q.x);
            qp[4*s+1] = pack2(q.y, q.y);
            qp[4*s+2] = pack2(q.z, q.z);
            qp[4*s+3] = pack2(q.w, q.w);
        }

        // ---- D init = broadcast b2 (MMA accumulates onto it) ----
        float D[2][8][4];
        #pragma unroll
        for (int nt = 0; nt < 8; ++nt) {
            float e0, e1; unpack2(sB2p[4*nt + c], e0, e1);
            D[0][nt][0] = e0; D[0][nt][1] = e1; D[0][nt][2] = e0; D[0][nt][3] = e1;
            D[1][nt][0] = e0; D[1][nt][1] = e1; D[1][nt][2] = e0; D[1][nt][3] = e1;
        }

        #pragma unroll
        for (int kt = 0; kt < 4; ++kt) {
            // ---- A fragments in place: layer-1 fp32 + exact bf16 hi/lo split ----
            uint32_t ahi[2][4], alo[2][4];
            #pragma unroll
            for (int h = 0; h < 2; ++h) {
                int jp = c + 8 * kt + 4 * h;
                ulonglong2 wA = sW1a[jp], wB = sW1b[jp];
                ull bb = sb1p[jp];
                #pragma unroll
                for (int s = 0; s < 4; ++s) {
                    ull z = fma2(wA.x, qp[4*s+0], bb);
                    z = fma2(wA.y, qp[4*s+1], z);
                    z = fma2(wB.x, qp[4*s+2], z);
                    z = fma2(wB.y, qp[4*s+3], z);
                    ull mm = fma2(z, SLOPE2, 0ull);        // 0.01*z packed
                    float z0, z1, m0, m1;
                    unpack2(z, z0, z1); unpack2(mm, m0, m1);
                    float e = fmaxf(z0, m0), o = fmaxf(z1, m1);
                    uint32_t hv;
                    asm("cvt.rn.bf16x2.f32 %0, %1, %2;" : "=r"(hv) : "f"(o), "f"(e));
                    float ef = __uint_as_float(hv << 16);
                    float of = __uint_as_float(hv & 0xFFFF0000u);
                    float le = e - ef, lod = o - of;       // exact residuals
                    uint32_t lv;
                    asm("cvt.rn.bf16x2.f32 %0, %1, %2;" : "=r"(lv) : "f"(lod), "f"(le));
                    int m = s >> 1, half = s & 1;
                    ahi[m][2*h + half] = hv;
                    alo[m][2*h + half] = lv;
                }
            }

            // ---- B via ldmatrix, 3-product compensated MMA ----
            #pragma unroll
            for (int p = 0; p < 4; ++p) {
                int mat = lane >> 3, rin = lane & 7;
                int nrow = (2*p + (mat >> 1)) * 8 + rin;
                int kseg = 2*kt + (mat & 1);
                uint32_t off = SW128((uint32_t)(nrow * 128 + kseg * 16));
                uint32_t bh0, bh1, bh2, bh3, bl0, bl1, bl2, bl3;
                asm volatile("ldmatrix.sync.aligned.m8n8.x4.shared.b16 {%0,%1,%2,%3}, [%4];"
                    : "=r"(bh0), "=r"(bh1), "=r"(bh2), "=r"(bh3) : "r"(whi + off));
                asm volatile("ldmatrix.sync.aligned.m8n8.x4.shared.b16 {%0,%1,%2,%3}, [%4];"
                    : "=r"(bl0), "=r"(bl1), "=r"(bl2), "=r"(bl3) : "r"(wlo + off));
                #pragma unroll
                for (int m = 0; m < 2; ++m) {
                    MMA16816(D[m][2*p],     ahi[m], bh0, bh1);
                    MMA16816(D[m][2*p],     ahi[m], bl0, bl1);
                    MMA16816(D[m][2*p],     alo[m], bh0, bh1);
                    MMA16816(D[m][2*p + 1], ahi[m], bh2, bh3);
                    MMA16816(D[m][2*p + 1], ahi[m], bl2, bl3);
                    MMA16816(D[m][2*p + 1], alo[m], bh2, bh3);
                }
            }
        }

        // ---- packed epilogue: leaky + head dots over column pairs ----
        float rLd0[4], rLd1[4], rLo[4];
        #pragma unroll
        for (int m = 0; m < 2; ++m) {
            ull a0_0 = 0ull, a1_0 = 0ull, a2_0 = 0ull;   // row slot 2m
            ull a0_1 = 0ull, a1_1 = 0ull, a2_1 = 0ull;   // row slot 2m+1
            #pragma unroll
            for (int nt = 0; nt < 8; ++nt) {
                int jp = 4*nt + c;
                ulonglong2 hd = sHd[jp];
                ull lop = sLoP[jp];
                // half 0 (row rq + 16m): b2 already inside D
                {
                    ull p = pack2(D[m][nt][0], D[m][nt][1]);
                    ull mm = fma2(p, SLOPE2, 0ull);
                    float z0, z1, m0, m1;
                    unpack2(p, z0, z1); unpack2(mm, m0, m1);
                    ull hp = pack2(fmaxf(z0, m0), fmaxf(z1, m1));
                    a0_0 = fma2(hd.x, hp, a0_0);
                    a1_0 = fma2(hd.y, hp, a1_0);
                    a2_0 = fma2(lop,  hp, a2_0);
                }
                // half 1 (row rq + 16m + 8)
                {
                    ull p = pack2(D[m][nt][2], D[m][nt][3]);
                    ull mm = fma2(p, SLOPE2, 0ull);
                    float z0, z1, m0, m1;
                    unpack2(p, z0, z1); unpack2(mm, m0, m1);
                    ull hp = pack2(fmaxf(z0, m0), fmaxf(z1, m1));
                    a0_1 = fma2(hd.x, hp, a0_1);
                    a1_1 = fma2(hd.y, hp, a1_1);
                    a2_1 = fma2(lop,  hp, a2_1);
                }
            }
            float u, v;
            unpack2(a0_0, u, v); rLd0[2*m]   = u + v;
            unpack2(a1_0, u, v); rLd1[2*m]   = u + v;
            unpack2(a2_0, u, v); rLo[2*m]    = u + v;
            unpack2(a0_1, u, v); rLd0[2*m+1] = u + v;
            unpack2(a1_1, u, v); rLd1[2*m+1] = u + v;
            unpack2(a2_1, u, v); rLo[2*m+1]  = u + v;
        }

        // ---- quad all-reduce; lane c finalizes row rq + 8c ----
        float v0 = 0.f, v1 = 0.f, v2 = 0.f;
        #pragma unroll
        for (int s = 0; s < 4; ++s) {
            float a0 = rLd0[s], a1 = rLd1[s], a2 = rLo[s];
            #pragma unroll
            for (int msk = 1; msk <= 2; msk <<= 1) {
                a0 += __shfl_xor_sync(0xFFFFFFFFu, a0, msk);
                a1 += __shfl_xor_sync(0xFFFFFFFFu, a1, msk);
                a2 += __shfl_xor_sync(0xFFFFFFFFu, a2, msk);
            }
            if (c == s) { v0 = a0; v1 = a1; v2 = a2; }
        }

        int g = gbase + rq + 8 * c;
        if (g < n) {
            float Ld0 = softplus_f(v0 + sbh[0]);
            float Ld1 = softplus_f(v1 + sbh[1]);
            float Lo  = v2 + sbh[2];
            float H00 = fmaf(Ld0, Ld0, 1e-9f);
            float H01 = Ld0 * Lo;
            float H11 = fmaf(Lo, Lo, fmaf(Ld1, Ld1, 1e-9f));
            out[g] = make_float4(H00, H01, H01, H11);
        }
    }
}

extern "C" void kernel_launch(void* const* d_in, const int* in_sizes, int n_in,
                              void* d_out, int out_size) {
    const float4* x  = (const float4*)d_in[0];
    const float* W1  = (const float*)d_in[1];
    const float* b1  = (const float*)d_in[2];
    const float* W2  = (const float*)d_in[3];
    const float* b2  = (const float*)d_in[4];
    const float* WLd = (const float*)d_in[5];
    const float* bLd = (const float*)d_in[6];
    const float* WLo = (const float*)d_in[7];
    const float* bLo = (const float*)d_in[8];

    int n = in_sizes[0] / 4;
    int ntiles = (n + 127) >> 7;
    int blocks = 456;                  // 3 CTAs x 152 SMs persistent; ~18 tiles/CTA
    if (blocks > ntiles) blocks = ntiles;
    dln_mma<<<blocks, 128, DYN_SMEM>>>(x, W1, b1, W2, b2, WLd, bLd, WLo, bLo,
                                       (float4*)d_out, n);
}